// round 3
// baseline (speedup 1.0000x reference)
#include <cuda_runtime.h>

#define T_LEN   16777216
#define BLOCK   256
#define ITEMS   32
#define TILE    (BLOCK * ITEMS)          // 8192
#define NTILES  (T_LEN / TILE)           // 2048
#define FULLMASK 0xffffffffu

// Decoupled-lookback state (device globals: no allocation allowed)
__device__ unsigned int g_ctr;
__device__ int   g_flag[NTILES];                 // 0=invalid 1=partial 2=inclusive
__device__ float g_pA[NTILES], g_pB[NTILES];     // partial aggregates
__device__ float g_iA[NTILES], g_iB[NTILES];     // inclusive prefixes

__global__ void ses_init() {
    int i = blockIdx.x * blockDim.x + threadIdx.x;
    if (i < NTILES) g_flag[i] = 0;
    if (i == 0) g_ctr = 0u;
}

__global__ __launch_bounds__(BLOCK) void ses_scan(
    const float* __restrict__ y, const float* __restrict__ alpha_p,
    float* __restrict__ out)
{
    __shared__ float sh_wA[BLOCK / 32], sh_wB[BLOCK / 32];
    __shared__ float sh_aggA, sh_aggB, sh_carry;
    __shared__ unsigned sh_tile;

    const int tid  = threadIdx.x;
    const int lane = tid & 31;
    const int wid  = tid >> 5;

    // Dynamic tile assignment: tiles are acquired in increasing order, so every
    // predecessor of a running tile is itself running or finished (no deadlock).
    if (tid == 0) sh_tile = atomicAdd(&g_ctr, 1u);
    __syncthreads();
    const int tile = (int)sh_tile;

    const float alpha = __ldg(alpha_p);
    const float a = 1.0f - alpha;

    const long long base = (long long)tile * TILE + (long long)tid * ITEMS;

    // ---- load 32 contiguous elements per thread (8x float4) ----
    float v[ITEMS];
    {
        const float4* p = reinterpret_cast<const float4*>(y + base);
        #pragma unroll
        for (int i = 0; i < ITEMS / 4; i++) {
            float4 q = p[i];
            v[4*i+0] = q.x; v[4*i+1] = q.y; v[4*i+2] = q.z; v[4*i+3] = q.w;
        }
    }

    // ---- thread-local scan with zero carry-in ----
    // element t: (a_t, b_t) = (1-alpha, alpha*y_t), except global t=0: (0, y_0)
    float A, B;
    {
        float p = 0.f, Aa = 1.f;
        const bool first = (base == 0);
        #pragma unroll
        for (int i = 0; i < ITEMS; i++) {
            float aa = a, bb = alpha * v[i];
            if (first && i == 0) { aa = 0.f; bb = v[0]; }
            p = fmaf(aa, p, bb);
            Aa *= aa;
            v[i] = p;                    // stash local partial
        }
        A = Aa; B = p;
    }

    // ---- warp inclusive scan of (A,B): combine(e1,e2) = (A1*A2, A2*B1 + B2) ----
    #pragma unroll
    for (int d = 1; d < 32; d <<= 1) {
        float pA = __shfl_up_sync(FULLMASK, A, d);
        float pB = __shfl_up_sync(FULLMASK, B, d);
        if (lane >= d) { B = fmaf(A, pB, B); A = pA * A; }
    }
    // lane-exclusive
    float exA = __shfl_up_sync(FULLMASK, A, 1);
    float exB = __shfl_up_sync(FULLMASK, B, 1);
    if (lane == 0) { exA = 1.f; exB = 0.f; }

    if (lane == 31) { sh_wA[wid] = A; sh_wB[wid] = B; }
    __syncthreads();

    // warp prefix: combine aggregates of warps 0..wid-1 (in temporal order)
    float WA = 1.f, WB = 0.f;
    for (int w = 0; w < wid; w++) {
        float wA = sh_wA[w], wB = sh_wB[w];
        WB = fmaf(wA, WB, wB);   // combine(W, warp_w): wA*WB + wB
        WA = WA * wA;
    }
    // thread-exclusive within tile: combine(W, ex)
    const float TexB = fmaf(exA, WB, exB);
    const float TexA = WA * exA;

    // ---- publish tile aggregate ----
    if (tid == 0) {
        float gA = 1.f, gB = 0.f;
        #pragma unroll
        for (int w = 0; w < BLOCK / 32; w++) {
            float wA = sh_wA[w], wB = sh_wB[w];
            gB = fmaf(wA, gB, wB);
            gA = gA * wA;
        }
        sh_aggA = gA; sh_aggB = gB;
        if (tile == 0) {
            __stcg(&g_iA[0], gA);
            __stcg(&g_iB[0], gB);
            __threadfence();
            atomicExch(&g_flag[0], 2);
            sh_carry = 0.f;
        } else {
            __stcg(&g_pA[tile], gA);
            __stcg(&g_pB[tile], gB);
            __threadfence();
            atomicExch(&g_flag[tile], 1);
        }
    }

    // ---- warp-parallel decoupled lookback (warp 0 only) ----
    if (wid == 0 && tile > 0) {
        __syncwarp();
        float accA = 1.f, accB = 0.f;      // aggregate of consumed suffix tiles
        int pred = tile - 1;
        for (;;) {
            const int idx = pred - lane;   // lane 0 = nearest predecessor (latest)
            int f;
            if (idx >= 0) {
                do { f = *((volatile int*)&g_flag[idx]); } while (f == 0);
            } else {
                f = 2;                     // before tile 0: inclusive identity
            }
            __threadfence();
            float mA, mB;
            if (idx < 0)     { mA = 1.f;                mB = 0.f; }
            else if (f == 2) { mA = __ldcg(&g_iA[idx]); mB = __ldcg(&g_iB[idx]); }
            else             { mA = __ldcg(&g_pA[idx]); mB = __ldcg(&g_pB[idx]); }

            const unsigned bal = __ballot_sync(FULLMASK, f == 2);
            const int m = bal ? (__ffs(bal) - 1) : 32;   // closest inclusive lane
            const int start = (m < 32) ? m : 31;

            // combine window tiles earliest->latest: lane start (earliest) .. lane 0
            // c = combine(c, s_L):  (cA*sA, sA*cB + sB)   [FIX: was swapped]
            float cA = 1.f, cB = 0.f;
            for (int L = start; L >= 0; --L) {
                float sA = __shfl_sync(FULLMASK, mA, L);
                float sB = __shfl_sync(FULLMASK, mB, L);
                cB = fmaf(sA, cB, sB);
                cA = cA * sA;
            }
            // acc = combine(window, acc): window precedes acc in time
            float nB = fmaf(accA, cB, accB);
            accA = cA * accA;
            accB = nB;

            if (m < 32) break;             // anchored on an inclusive prefix
            pred -= 32;
        }
        if (lane == 0) {
            const float gA = sh_aggA, gB = sh_aggB;
            __stcg(&g_iA[tile], accA * gA);
            __stcg(&g_iB[tile], fmaf(gA, accB, gB));
            __threadfence();
            atomicExch(&g_flag[tile], 2);
            sh_carry = accB;               // s_{tileStart-1}
        }
    }
    __syncthreads();

    // ---- fixup and store ----
    const float c = fmaf(TexA, sh_carry, TexB);   // s just before this thread
    float pw = a;
    #pragma unroll
    for (int i = 0; i < ITEMS; i++) {
        v[i] = fmaf(c, pw, v[i]);
        pw *= a;
    }

    // output has T_LEN-1 elements: never write global index T_LEN-1
    if (base + ITEMS <= (long long)(T_LEN - 1)) {
        float4* op = reinterpret_cast<float4*>(out + base);
        #pragma unroll
        for (int i = 0; i < ITEMS / 4; i++)
            op[i] = make_float4(v[4*i+0], v[4*i+1], v[4*i+2], v[4*i+3]);
    } else {
        #pragma unroll
        for (int i = 0; i < ITEMS; i++) {
            const long long g = base + i;
            if (g < (long long)(T_LEN - 1)) out[g] = v[i];
        }
    }
}

extern "C" void kernel_launch(void* const* d_in, const int* in_sizes, int n_in,
                              void* d_out, int out_size) {
    const float* y     = (const float*)d_in[0];   // timeseries, T_LEN fp32
    const float* alpha = (const float*)d_in[1];   // 1 fp32
    float* out = (float*)d_out;                   // T_LEN-1 fp32
    (void)in_sizes; (void)n_in; (void)out_size;

    ses_init<<<(NTILES + 255) / 256, 256>>>();
    ses_scan<<<NTILES, BLOCK>>>(y, alpha, out);
}

// round 4
// speedup vs baseline: 1.1780x; 1.1780x over previous
#include <cuda_runtime.h>

#define T_LEN   16777216
#define BLOCK   256
#define ITEMS   32
#define TILE    (BLOCK * ITEMS)          // 8192
#define NTILES  (T_LEN / TILE)           // 2048
#define FULLMASK 0xffffffffu

// Decoupled-lookback state (device globals: no allocation allowed)
__device__ unsigned int g_ctr;
__device__ int   g_flag[NTILES];                 // 0=invalid 1=partial 2=inclusive
__device__ float g_pA[NTILES], g_pB[NTILES];     // partial aggregates
__device__ float g_iA[NTILES], g_iB[NTILES];     // inclusive prefixes

__global__ void ses_init() {
    int i = blockIdx.x * blockDim.x + threadIdx.x;
    if (i < NTILES) g_flag[i] = 0;
    if (i == 0) g_ctr = 0u;
}

__global__ __launch_bounds__(BLOCK) void ses_scan(
    const float* __restrict__ y, const float* __restrict__ alpha_p,
    float* __restrict__ out)
{
    __shared__ float sh_wA[BLOCK / 32], sh_wB[BLOCK / 32];
    __shared__ float sh_aggA, sh_aggB, sh_carry;
    __shared__ unsigned sh_tile;

    const int tid  = threadIdx.x;
    const int lane = tid & 31;
    const int wid  = tid >> 5;

    // Dynamic tile assignment: tiles acquired in increasing order, so every
    // predecessor of a running tile is itself running or finished (no deadlock).
    if (tid == 0) sh_tile = atomicAdd(&g_ctr, 1u);
    __syncthreads();
    const int tile = (int)sh_tile;

    const float alpha = __ldg(alpha_p);
    const float a = 1.0f - alpha;

    const long long base = (long long)tile * TILE + (long long)tid * ITEMS;

    // ---- load 32 contiguous elements per thread (8x float4) ----
    float v[ITEMS];
    {
        const float4* p = reinterpret_cast<const float4*>(y + base);
        #pragma unroll
        for (int i = 0; i < ITEMS / 4; i++) {
            float4 q = p[i];
            v[4*i+0] = q.x; v[4*i+1] = q.y; v[4*i+2] = q.z; v[4*i+3] = q.w;
        }
    }

    // ---- thread-local scan with zero carry-in ----
    // element t: (a_t, b_t) = (1-alpha, alpha*y_t), except global t=0: (0, y_0)
    float A, B;
    {
        float p = 0.f, Aa = 1.f;
        const bool first = (base == 0);
        #pragma unroll
        for (int i = 0; i < ITEMS; i++) {
            float aa = a, bb = alpha * v[i];
            if (first && i == 0) { aa = 0.f; bb = v[0]; }
            p = fmaf(aa, p, bb);
            Aa *= aa;
            v[i] = p;                    // stash local partial
        }
        A = Aa; B = p;
    }

    // ---- warp inclusive scan of (A,B): combine(e1,e2) = (A1*A2, A2*B1 + B2) ----
    #pragma unroll
    for (int d = 1; d < 32; d <<= 1) {
        float pA = __shfl_up_sync(FULLMASK, A, d);
        float pB = __shfl_up_sync(FULLMASK, B, d);
        if (lane >= d) { B = fmaf(A, pB, B); A = pA * A; }
    }
    // lane-exclusive
    float exA = __shfl_up_sync(FULLMASK, A, 1);
    float exB = __shfl_up_sync(FULLMASK, B, 1);
    if (lane == 0) { exA = 1.f; exB = 0.f; }

    if (lane == 31) { sh_wA[wid] = A; sh_wB[wid] = B; }
    __syncthreads();

    // warp prefix: combine aggregates of warps 0..wid-1 (in temporal order)
    float WA = 1.f, WB = 0.f;
    for (int w = 0; w < wid; w++) {
        float wA = sh_wA[w], wB = sh_wB[w];
        WB = fmaf(wA, WB, wB);   // combine(W, warp_w): wA*WB + wB
        WA = WA * wA;
    }
    // thread-exclusive within tile: combine(W, ex)
    const float TexB = fmaf(exA, WB, exB);
    const float TexA = WA * exA;

    // ---- publish tile aggregate ----
    if (tid == 0) {
        float gA = 1.f, gB = 0.f;
        #pragma unroll
        for (int w = 0; w < BLOCK / 32; w++) {
            float wA = sh_wA[w], wB = sh_wB[w];
            gB = fmaf(wA, gB, wB);
            gA = gA * wA;
        }
        sh_aggA = gA; sh_aggB = gB;
        if (tile == 0) {
            __stcg(&g_iA[0], gA);
            __stcg(&g_iB[0], gB);
            __threadfence();
            atomicExch(&g_flag[0], 2);
            sh_carry = 0.f;
        } else {
            __stcg(&g_pA[tile], gA);
            __stcg(&g_pB[tile], gB);
            __threadfence();
            atomicExch(&g_flag[tile], 1);
        }
    }

    // ---- warp-parallel decoupled lookback (warp 0 only) ----
    if (wid == 0 && tile > 0) {
        __syncwarp();
        float accA = 1.f, accB = 0.f;      // aggregate of consumed suffix tiles
        int pred = tile - 1;
        for (;;) {
            const int idx = pred - lane;   // lane 0 = nearest predecessor (latest)
            int f;
            if (idx >= 0) {
                do { f = *((volatile int*)&g_flag[idx]); } while (f == 0);
            } else {
                f = 2;                     // before tile 0: inclusive identity
            }
            __threadfence();
            float mA, mB;
            if (idx < 0)     { mA = 1.f;                mB = 0.f; }
            else if (f == 2) { mA = __ldcg(&g_iA[idx]); mB = __ldcg(&g_iB[idx]); }
            else             { mA = __ldcg(&g_pA[idx]); mB = __ldcg(&g_pB[idx]); }

            const unsigned bal = __ballot_sync(FULLMASK, f == 2);
            const int m = bal ? (__ffs(bal) - 1) : 32;   // closest inclusive lane
            const int start = (m < 32) ? m : 31;

            // combine window tiles earliest->latest: lane start (earliest) .. lane 0
            // c = combine(c, s_L):  (cA*sA, sA*cB + sB)
            float cA = 1.f, cB = 0.f;
            for (int L = start; L >= 0; --L) {
                float sA = __shfl_sync(FULLMASK, mA, L);
                float sB = __shfl_sync(FULLMASK, mB, L);
                cB = fmaf(sA, cB, sB);
                cA = cA * sA;
            }
            // acc = combine(window, acc): window precedes acc in time
            float nB = fmaf(accA, cB, accB);
            accA = cA * accA;
            accB = nB;

            // EARLY TERMINATION: accA == 0 means the result is exactly
            // independent of all earlier tiles (combine(X, acc) = (0, accB)).
            // For a^TILE underflow (virtually all alpha) this fires after one
            // window containing only the immediate predecessor's PARTIAL —
            // collapsing the serial inclusive-propagation chain.
            if (m < 32 || accA == 0.0f) break;
            pred -= 32;
        }
        if (lane == 0) {
            const float gA = sh_aggA, gB = sh_aggB;
            __stcg(&g_iA[tile], accA * gA);
            __stcg(&g_iB[tile], fmaf(gA, accB, gB));
            __threadfence();
            atomicExch(&g_flag[tile], 2);
            sh_carry = accB;               // s_{tileStart-1}
        }
    }
    __syncthreads();

    // ---- fixup and store ----
    const float c = fmaf(TexA, sh_carry, TexB);   // s just before this thread
    float pw = a;
    #pragma unroll
    for (int i = 0; i < ITEMS; i++) {
        v[i] = fmaf(c, pw, v[i]);
        pw *= a;
    }

    // output has T_LEN-1 elements: never write global index T_LEN-1.
    // Streaming stores: output is never re-read, keep it out of L2's way.
    if (base + ITEMS <= (long long)(T_LEN - 1)) {
        float4* op = reinterpret_cast<float4*>(out + base);
        #pragma unroll
        for (int i = 0; i < ITEMS / 4; i++)
            __stcs(op + i, make_float4(v[4*i+0], v[4*i+1], v[4*i+2], v[4*i+3]));
    } else {
        #pragma unroll
        for (int i = 0; i < ITEMS; i++) {
            const long long g = base + i;
            if (g < (long long)(T_LEN - 1)) __stcs(out + g, v[i]);
        }
    }
}

extern "C" void kernel_launch(void* const* d_in, const int* in_sizes, int n_in,
                              void* d_out, int out_size) {
    const float* y     = (const float*)d_in[0];   // timeseries, T_LEN fp32
    const float* alpha = (const float*)d_in[1];   // 1 fp32
    float* out = (float*)d_out;                   // T_LEN-1 fp32
    (void)in_sizes; (void)n_in; (void)out_size;

    ses_init<<<(NTILES + 255) / 256, 256>>>();
    ses_scan<<<NTILES, BLOCK>>>(y, alpha, out);
}

// round 8
// speedup vs baseline: 1.5311x; 1.2998x over previous
#include <cuda_runtime.h>

#define T_LEN   16777216
#define BLOCK   256
#define ITEMS   32
#define TILE    (BLOCK * ITEMS)          // 8192
#define NTILES  (T_LEN / TILE)           // 2048
#define FULLMASK 0xffffffffu

// Decoupled-lookback state (device globals: no allocation allowed)
__device__ unsigned int g_ctr;
__device__ int   g_flag[NTILES];                 // 0=invalid 1=partial 2=inclusive
__device__ float g_pA[NTILES], g_pB[NTILES];     // partial aggregates
__device__ float g_iA[NTILES], g_iB[NTILES];     // inclusive prefixes

__global__ void ses_init() {
    int i = blockIdx.x * blockDim.x + threadIdx.x;
    if (i < NTILES) g_flag[i] = 0;
    if (i == 0) g_ctr = 0u;
}

__global__ __launch_bounds__(BLOCK) void ses_scan(
    const float* __restrict__ y, const float* __restrict__ alpha_p,
    float* __restrict__ out)
{
    // Padded transpose buffer: physical float index = L + 4*(L>>5).
    // Blocked quad i of thread t  -> float4 slot 9*t + i      (conflict-free)
    // Striped quad Q = j*BLOCK+t  -> float4 slot Q + (Q>>3)   (conflict-free)
    __shared__ float sbuf[TILE + TILE / 8];      // 9216 floats = 36 KB
    __shared__ float sh_wB[BLOCK / 32];
    __shared__ float sh_carry;
    __shared__ unsigned sh_tile;

    const int tid  = threadIdx.x;
    const int lane = tid & 31;
    const int wid  = tid >> 5;

    // Dynamic tile ids: acquired in increasing order -> lookback never deadlocks.
    if (tid == 0) sh_tile = atomicAdd(&g_ctr, 1u);
    __syncthreads();
    const int tile = (int)sh_tile;

    const float alpha = __ldg(alpha_p);
    const float a = 1.0f - alpha;

    float4* s4 = reinterpret_cast<float4*>(sbuf);

    // ---- phase 1: striped coalesced load -> SMEM (transpose in) ----
    {
        const float4* yin = reinterpret_cast<const float4*>(y) + (size_t)tile * (TILE / 4);
        #pragma unroll
        for (int j = 0; j < 8; j++) {
            const int Q = j * BLOCK + tid;
            s4[Q + (Q >> 3)] = yin[Q];
        }
    }
    __syncthreads();

    // ---- phase 2: blocked read + thread-local serial scan ----
    float v[ITEMS];
    #pragma unroll
    for (int i = 0; i < 8; i++) {
        float4 q = s4[9 * tid + i];
        v[4*i+0] = q.x; v[4*i+1] = q.y; v[4*i+2] = q.z; v[4*i+3] = q.w;
    }

    // element t: (a, alpha*y_t); global t=0 pinned to (0, y_0)
    float B;
    {
        float p = 0.f;
        const bool first = (tile == 0 && tid == 0);
        #pragma unroll
        for (int i = 0; i < ITEMS; i++) {
            float aa = a, bb = alpha * v[i];
            if (first && i == 0) { aa = 0.f; bb = v[0]; }
            p = fmaf(aa, p, bb);
            v[i] = p;                        // local partial (zero carry-in)
        }
        B = p;
    }

    // constant-multiplier powers
    float a2 = a * a, a4 = a2 * a2, a8 = a4 * a4, a16 = a8 * a8, a32 = a16 * a16;

    // ---- warp inclusive scan of B only; window-A is closed form a^(32d) ----
    // (for lanes >= d the d-lane window never contains global element 0)
    float m = a32;
    #pragma unroll
    for (int d = 1; d < 32; d <<= 1) {
        float pB = __shfl_up_sync(FULLMASK, B, d);
        if (lane >= d) B = fmaf(m, pB, B);
        m = m * m;
    }
    const float A1024 = m;                   // a^1024 = full-warp A
    float exB = __shfl_up_sync(FULLMASK, B, 1);
    if (lane == 0) exB = 0.f;
    if (lane == 31) sh_wB[wid] = B;
    __syncthreads();

    // cross-warp B prefix (identity at w=0 makes warp-0-of-tile-0's A irrelevant)
    float WB = 0.f;
    for (int w = 0; w < wid; w++) WB = fmaf(A1024, WB, sh_wB[w]);

    // exA = a^(32*lane) via binary exponentiation
    float exA = 1.f;
    { float bp = a32; int e = lane;
      #pragma unroll
      for (int k = 0; k < 5; k++) { if (e & 1) exA *= bp; bp *= bp; e >>= 1; } }
    const float TexB = fmaf(exA, WB, exB);   // thread-exclusive B within tile
    // TexA = a^(32*tid) = exA * A1024^wid (only ever multiplies the carry;
    // tile 0's carry is 0, so the formal zero-prefix there is immaterial)
    float TexA = exA;
    { float wp = A1024; int e = wid;
      #pragma unroll
      for (int k = 0; k < 3; k++) { if (e & 1) TexA *= wp; wp *= wp; e >>= 1; } }

    // ---- publish tile aggregate ----
    float aggA = 0.f, aggB = 0.f;            // live in warp-0 lane-0 registers
    if (tid == 0) {
        float gB = 0.f;
        #pragma unroll
        for (int w = 0; w < BLOCK / 32; w++) gB = fmaf(A1024, gB, sh_wB[w]);
        float A8192 = A1024 * A1024; A8192 *= A8192; A8192 *= A8192;
        aggA = (tile == 0) ? 0.f : A8192;    // tile 0 truly has A = 0
        aggB = gB;
        if (tile == 0) {
            __stcg(&g_iA[0], 0.f);
            __stcg(&g_iB[0], gB);
            __threadfence();
            atomicExch(&g_flag[0], 2);
            sh_carry = 0.f;
        } else {
            __stcg(&g_pA[tile], A8192);
            __stcg(&g_pB[tile], gB);
            __threadfence();
            atomicExch(&g_flag[tile], 1);
        }
    }

    // ---- warp-parallel decoupled lookback (warp 0), early-exit on accA==0 ----
    if (wid == 0 && tile > 0) {
        __syncwarp();
        float accA = 1.f, accB = 0.f;
        int pred = tile - 1;
        for (;;) {
            const int idx = pred - lane;     // lane 0 = latest predecessor
            int f;
            if (idx >= 0) {
                f = *((volatile int*)&g_flag[idx]);
                while (f == 0) {
                    __nanosleep(32);         // HW sleep: keep L2 poll pressure low
                    f = *((volatile int*)&g_flag[idx]);
                }
            } else f = 2;
            __threadfence();
            float mA, mB;
            if (idx < 0)     { mA = 1.f;                mB = 0.f; }
            else if (f == 2) { mA = __ldcg(&g_iA[idx]); mB = __ldcg(&g_iB[idx]); }
            else             { mA = __ldcg(&g_pA[idx]); mB = __ldcg(&g_pB[idx]); }

            const unsigned bal = __ballot_sync(FULLMASK, f == 2);
            const int mm = bal ? (__ffs(bal) - 1) : 32;
            const int start = (mm < 32) ? mm : 31;

            // window combine earliest->latest: c = combine(c, s_L)
            float cA = 1.f, cB = 0.f;
            for (int L = start; L >= 0; --L) {
                float sA = __shfl_sync(FULLMASK, mA, L);
                float sB = __shfl_sync(FULLMASK, mB, L);
                cB = fmaf(sA, cB, sB);
                cA = cA * sA;
            }
            float nB = fmaf(accA, cB, accB);
            accA = cA * accA;
            accB = nB;

            // accA == 0 -> exactly independent of all earlier tiles
            if (mm < 32 || accA == 0.0f) break;
            pred -= 32;
        }
        if (lane == 0) {
            __stcg(&g_iA[tile], accA * aggA);
            __stcg(&g_iB[tile], fmaf(aggA, accB, aggB));
            __threadfence();
            atomicExch(&g_flag[tile], 2);
            sh_carry = accB;                 // level just before this tile
        }
    }
    __syncthreads();

    // ---- fixup ----
    const float c = fmaf(TexA, sh_carry, TexB);  // level just before this thread
    {
        float cp = c * a;
        #pragma unroll
        for (int i = 0; i < ITEMS; i++) { v[i] += cp; cp *= a; }
    }

    // ---- phase 3: blocked -> SMEM (own slots, no hazard), striped stores ----
    #pragma unroll
    for (int i = 0; i < 8; i++)
        s4[9 * tid + i] = make_float4(v[4*i+0], v[4*i+1], v[4*i+2], v[4*i+3]);
    __syncthreads();

    {
        float4* o4 = reinterpret_cast<float4*>(out) + (size_t)tile * (TILE / 4);
        if (tile != NTILES - 1) {
            #pragma unroll
            for (int j = 0; j < 8; j++) {
                const int Q = j * BLOCK + tid;
                __stcs(&o4[Q], s4[Q + (Q >> 3)]);
            }
        } else {
            // last tile: output length T_LEN-1, never write global index T_LEN-1
            const long long tbase = (long long)tile * TILE;
            #pragma unroll
            for (int j = 0; j < 8; j++) {
                const int Q = j * BLOCK + tid;
                float4 q = s4[Q + (Q >> 3)];
                const long long g = tbase + 4LL * Q;
                if (g + 4 <= (long long)(T_LEN - 1)) {
                    __stcs(&o4[Q], q);
                } else {
                    float* op = out + g;
                    if (g + 0 < (long long)(T_LEN - 1)) op[0] = q.x;
                    if (g + 1 < (long long)(T_LEN - 1)) op[1] = q.y;
                    if (g + 2 < (long long)(T_LEN - 1)) op[2] = q.z;
                    if (g + 3 < (long long)(T_LEN - 1)) op[3] = q.w;
                }
            }
        }
    }
}

extern "C" void kernel_launch(void* const* d_in, const int* in_sizes, int n_in,
                              void* d_out, int out_size) {
    const float* y     = (const float*)d_in[0];   // timeseries, T_LEN fp32
    const float* alpha = (const float*)d_in[1];   // 1 fp32
    float* out = (float*)d_out;                   // T_LEN-1 fp32
    (void)in_sizes; (void)n_in; (void)out_size;

    ses_init<<<(NTILES + 255) / 256, 256>>>();
    ses_scan<<<NTILES, BLOCK>>>(y, alpha, out);
}